// round 3
// baseline (speedup 1.0000x reference)
#include <cuda_runtime.h>
#include <cuda_bf16.h>
#include <cstdint>

// Problem constants
#define BATCH 128
#define NSEQ  384
#define MSEQ  384
#define DDIM  128
#define INF_V 1000000.0f

// ---------------------------------------------------------------------------
// Scratch (static __device__ globals — no allocation)
// g_D is stored TRANSPOSED: g_D[b][j][i] = ||a_i - b_j||^2, contiguous in i.
// ---------------------------------------------------------------------------
__device__ float g_D[(size_t)BATCH * NSEQ * MSEQ];
__device__ float g_na[BATCH * NSEQ];                 // ||a_i||^2
__device__ float g_nb[BATCH * MSEQ];                 // ||b_j||^2

// ---------------------------------------------------------------------------
// Kernel 1: row norms of a and b
// ---------------------------------------------------------------------------
__global__ void norm_kernel(const float* __restrict__ A, const float* __restrict__ Bm) {
    int idx = blockIdx.x * blockDim.x + threadIdx.x;
    const float* src;
    float* dst;
    int row;
    if (idx < BATCH * NSEQ) { src = A;  dst = g_na; row = idx; }
    else                    { src = Bm; dst = g_nb; row = idx - BATCH * NSEQ; }
    const float4* p = (const float4*)(src + (size_t)row * DDIM);
    float s = 0.0f;
#pragma unroll
    for (int i = 0; i < DDIM / 4; i++) {
        float4 v = p[i];
        s += v.x * v.x + v.y * v.y + v.z * v.z + v.w * v.w;
    }
    dst[row] = s;
}

// ---------------------------------------------------------------------------
// Kernel 2: batched pairwise distances via tiled fp32 GEMM, TRANSPOSED output.
// Row dimension = b_j (MSEQ), col dimension = a_i (NSEQ):
//   g_D[b][j][i] = nb[j] + na[i] - 2*dot(b_j, a_i)
// Tile: 128x128, BK=16, 256 threads, 8x8 microtile.
// ---------------------------------------------------------------------------
#define BM 128
#define BN 128
#define BK 16
#define PAD 132

__global__ __launch_bounds__(256) void dist_kernel(const float* __restrict__ Bm,
                                                   const float* __restrict__ A) {
    __shared__ float As[BK][PAD];   // rows of Bm (the "M" side now)
    __shared__ float Bs[BK][PAD];   // rows of A  (the "N" side now)

    const int b = blockIdx.z;
    const int rowTile = blockIdx.y * BM;   // j tile
    const int colTile = blockIdx.x * BN;   // i tile

    const float* rb = Bm + ((size_t)b * MSEQ + rowTile) * DDIM;
    const float* ra = A  + ((size_t)b * NSEQ + colTile) * DDIM;

    const int t  = threadIdx.x;
    const int tm = (t / 16) * 8;
    const int tn = (t % 16) * 8;

    const int q  = t & 3;
    const int r0 = t >> 2;

    float acc[8][8];
#pragma unroll
    for (int x = 0; x < 8; x++)
#pragma unroll
        for (int y = 0; y < 8; y++) acc[x][y] = 0.0f;

    for (int k0 = 0; k0 < DDIM; k0 += BK) {
#pragma unroll
        for (int p = 0; p < 2; p++) {
            int r = r0 + p * 64;
            float4 va = *(const float4*)(rb + (size_t)r * DDIM + k0 + q * 4);
            As[q * 4 + 0][r] = va.x;
            As[q * 4 + 1][r] = va.y;
            As[q * 4 + 2][r] = va.z;
            As[q * 4 + 3][r] = va.w;
            float4 vb = *(const float4*)(ra + (size_t)r * DDIM + k0 + q * 4);
            Bs[q * 4 + 0][r] = vb.x;
            Bs[q * 4 + 1][r] = vb.y;
            Bs[q * 4 + 2][r] = vb.z;
            Bs[q * 4 + 3][r] = vb.w;
        }
        __syncthreads();

#pragma unroll
        for (int kk = 0; kk < BK; kk++) {
            float4 a0 = *(const float4*)&As[kk][tm];
            float4 a1 = *(const float4*)&As[kk][tm + 4];
            float4 b0 = *(const float4*)&Bs[kk][tn];
            float4 b1 = *(const float4*)&Bs[kk][tn + 4];
            float am[8] = {a0.x, a0.y, a0.z, a0.w, a1.x, a1.y, a1.z, a1.w};
            float bn[8] = {b0.x, b0.y, b0.z, b0.w, b1.x, b1.y, b1.z, b1.w};
#pragma unroll
            for (int x = 0; x < 8; x++)
#pragma unroll
                for (int y = 0; y < 8; y++) acc[x][y] += am[x] * bn[y];
        }
        __syncthreads();
    }

    // Epilogue: D[b][j][i] = nb[j] + na[i] - 2*dot
    float nbv[8], nav[8];
#pragma unroll
    for (int x = 0; x < 8; x++) nbv[x] = g_nb[b * MSEQ + rowTile + tm + x];
#pragma unroll
    for (int y = 0; y < 8; y++) nav[y] = g_na[b * NSEQ + colTile + tn + y];

    float* Dp = g_D + ((size_t)b * MSEQ + rowTile + tm) * NSEQ + colTile + tn;
#pragma unroll
    for (int x = 0; x < 8; x++) {
        float4 o0, o1;
        o0.x = nbv[x] + nav[0] - 2.0f * acc[x][0];
        o0.y = nbv[x] + nav[1] - 2.0f * acc[x][1];
        o0.z = nbv[x] + nav[2] - 2.0f * acc[x][2];
        o0.w = nbv[x] + nav[3] - 2.0f * acc[x][3];
        o1.x = nbv[x] + nav[4] - 2.0f * acc[x][4];
        o1.y = nbv[x] + nav[5] - 2.0f * acc[x][5];
        o1.z = nbv[x] + nav[6] - 2.0f * acc[x][6];
        o1.w = nbv[x] + nav[7] - 2.0f * acc[x][7];
        *(float4*)(Dp + (size_t)x * NSEQ)     = o0;
        *(float4*)(Dp + (size_t)x * NSEQ + 4) = o1;
    }
}

// ---------------------------------------------------------------------------
// Kernel 3: soft-DTW anti-diagonal wavefront DP. One CTA per batch.
// Thread t owns column j=t+1. Its D stream g_D[b][j-1][*] is CONTIGUOUS;
// streamed through a 2x float4 register queue, prefetched 4-8 steps ahead.
// ---------------------------------------------------------------------------
__global__ __launch_bounds__(MSEQ) void dtw_kernel(float* __restrict__ out) {
    __shared__ float buf[3][MSEQ + 8];

    const int b = blockIdx.x;
    const int t = threadIdx.x;           // 0..383
    const int j = t + 1;                 // column 1..384
    const float* __restrict__ col = g_D + (size_t)b * MSEQ * NSEQ + (size_t)t * NSEQ;

    // Register queue: qa holds elements [0..3], qb holds [4..7] initially.
    float4 qa = *(const float4*)(col);
    float4 qb = *(const float4*)(col + 4);
    int c  = 0;       // consumed element count (= i-1 of next consume)
    int nl = 8;       // next element index to load

    buf[0][t] = INF_V;
    buf[1][t] = INF_V;
    buf[2][t] = INF_V;
    if (t == 0) {
        buf[0][MSEQ] = INF_V;
        buf[1][MSEQ] = INF_V;
        buf[2][MSEQ] = INF_V;
        buf[0][0] = 0.0f;                // R[0][0]
    }
    __syncthreads();

    int p2 = 0, p1 = 1, pc = 2;

    for (int k = 2; k <= NSEQ + MSEQ; k++) {
        const int i = k - j;
        const bool valid = (i >= 1) && (i <= NSEQ);

        float val;
        if (valid) {
            // smem reads first (independent of D stream)
            float rd = buf[p2][j - 1];   // diag
            float ru = buf[p1][j];       // up
            float rl = buf[p1][j - 1];   // left

            // pop D element c from register queue
            int ph = c & 3;
            float4 q = ((c >> 2) & 1) ? qb : qa;
            float d = (ph == 0) ? q.x : (ph == 1) ? q.y : (ph == 2) ? q.z : q.w;
            c++;
            if ((c & 3) == 0 && nl < NSEQ) {
                // refill the buffer we just exhausted (the one NOT now in use)
                if ((c >> 2) & 1) qa = *(const float4*)(col + nl);
                else              qb = *(const float4*)(col + nl);
                nl += 4;
            }

            float m = fminf(rd, fminf(ru, rl));
            float s = __expf(m - rd) + __expf(m - ru) + __expf(m - rl);
            val = d + m - __logf(s);
        } else {
            val = INF_V;
        }

        buf[pc][j] = val;
        if (t == 0) buf[pc][0] = INF_V;
        if (k == NSEQ + MSEQ && t == MSEQ - 1) out[b] = val;   // R[N][M]

        __syncthreads();
        int tmp = p2; p2 = p1; p1 = pc; pc = tmp;
    }
}

// ---------------------------------------------------------------------------
// Launch
// ---------------------------------------------------------------------------
extern "C" void kernel_launch(void* const* d_in, const int* in_sizes, int n_in,
                              void* d_out, int out_size) {
    const float* a = (const float*)d_in[0];
    const float* b = (const float*)d_in[1];
    float* out = (float*)d_out;

    norm_kernel<<<(2 * BATCH * NSEQ) / 256, 256>>>(a, b);

    dim3 gdist(NSEQ / BN, MSEQ / BM, BATCH);   // (3,3,128)
    dist_kernel<<<gdist, 256>>>(b, a);

    dtw_kernel<<<BATCH, MSEQ>>>(out);
}

// round 4
// speedup vs baseline: 1.7002x; 1.7002x over previous
#include <cuda_runtime.h>
#include <cuda_bf16.h>
#include <cstdint>

// Problem constants
#define BATCH 128
#define NSEQ  384
#define MSEQ  384
#define DDIM  128
#define INF_V 1000000.0f

// ---------------------------------------------------------------------------
// Scratch (static __device__ globals — no allocation)
// g_D TRANSPOSED: g_D[b][j][i] = ||a_i - b_j||^2, contiguous in i.
// ---------------------------------------------------------------------------
__device__ float g_D[(size_t)BATCH * NSEQ * MSEQ];
__device__ float g_na[BATCH * NSEQ];                 // ||a_i||^2
__device__ float g_nb[BATCH * MSEQ];                 // ||b_j||^2

// ---------------------------------------------------------------------------
// Packed fp32x2 helpers (Blackwell packed-FMA pipe; ptxas won't auto-fuse)
// ---------------------------------------------------------------------------
__device__ __forceinline__ void fma2(unsigned long long& d,
                                     unsigned long long a,
                                     unsigned long long b) {
    asm("fma.rn.f32x2 %0, %1, %2, %0;" : "+l"(d) : "l"(a), "l"(b));
}
__device__ __forceinline__ unsigned long long pack2(float x, float y) {
    unsigned long long r;
    asm("mov.b64 %0, {%1, %2};" : "=l"(r) : "f"(x), "f"(y));
    return r;
}
__device__ __forceinline__ float2 unpack2(unsigned long long v) {
    float lo, hi;
    asm("mov.b64 {%0, %1}, %2;" : "=f"(lo), "=f"(hi) : "l"(v));
    return make_float2(lo, hi);
}

// ---------------------------------------------------------------------------
// Kernel 1: row norms, 4 lanes per row + shfl reduce
// ---------------------------------------------------------------------------
__global__ void norm_kernel(const float* __restrict__ A, const float* __restrict__ Bm) {
    int gid = blockIdx.x * blockDim.x + threadIdx.x;   // 0 .. 4*2*BATCH*NSEQ-1
    int row = gid >> 2;
    int q   = gid & 3;
    const float* src;
    float* dst;
    int r;
    if (row < BATCH * NSEQ) { src = A;  dst = g_na; r = row; }
    else                    { src = Bm; dst = g_nb; r = row - BATCH * NSEQ; }
    const float4* p = (const float4*)(src + (size_t)r * DDIM + q * 32);
    float s = 0.0f;
#pragma unroll
    for (int i = 0; i < 8; i++) {
        float4 v = p[i];
        s += v.x * v.x + v.y * v.y + v.z * v.z + v.w * v.w;
    }
    s += __shfl_xor_sync(0xffffffffu, s, 1);
    s += __shfl_xor_sync(0xffffffffu, s, 2);
    if (q == 0) dst[r] = s;
}

// ---------------------------------------------------------------------------
// Kernel 2: batched pairwise distances, FFMA2 inner loop, TRANSPOSED output.
//   g_D[b][j][i] = nb[j] + na[i] - 2*dot(b_j, a_i)
// ---------------------------------------------------------------------------
#define BM 128
#define BN 128
#define BK 16
#define PAD 132

__global__ __launch_bounds__(256) void dist_kernel(const float* __restrict__ Bm,
                                                   const float* __restrict__ A) {
    __shared__ float As[BK][PAD];   // rows of Bm (j side)
    __shared__ float Bs[BK][PAD];   // rows of A  (i side)

    const int b = blockIdx.z;
    const int rowTile = blockIdx.y * BM;   // j tile
    const int colTile = blockIdx.x * BN;   // i tile

    const float* rb = Bm + ((size_t)b * MSEQ + rowTile) * DDIM;
    const float* ra = A  + ((size_t)b * NSEQ + colTile) * DDIM;

    const int t  = threadIdx.x;
    const int tm = (t / 16) * 8;
    const int tn = (t % 16) * 8;
    const int q  = t & 3;
    const int r0 = t >> 2;

    unsigned long long accp[8][4];   // 8 rows x 4 packed fp32 pairs (8 cols)
#pragma unroll
    for (int x = 0; x < 8; x++)
#pragma unroll
        for (int y = 0; y < 4; y++) accp[x][y] = 0ULL;

    for (int k0 = 0; k0 < DDIM; k0 += BK) {
#pragma unroll
        for (int p = 0; p < 2; p++) {
            int r = r0 + p * 64;
            float4 va = *(const float4*)(rb + (size_t)r * DDIM + k0 + q * 4);
            As[q * 4 + 0][r] = va.x;
            As[q * 4 + 1][r] = va.y;
            As[q * 4 + 2][r] = va.z;
            As[q * 4 + 3][r] = va.w;
            float4 vb = *(const float4*)(ra + (size_t)r * DDIM + k0 + q * 4);
            Bs[q * 4 + 0][r] = vb.x;
            Bs[q * 4 + 1][r] = vb.y;
            Bs[q * 4 + 2][r] = vb.z;
            Bs[q * 4 + 3][r] = vb.w;
        }
        __syncthreads();

#pragma unroll
        for (int kk = 0; kk < BK; kk++) {
            float4 a0 = *(const float4*)&As[kk][tm];
            float4 a1 = *(const float4*)&As[kk][tm + 4];
            ulonglong2 q0 = *(const ulonglong2*)&Bs[kk][tn];      // pairs (0,1),(2,3)
            ulonglong2 q1 = *(const ulonglong2*)&Bs[kk][tn + 4];  // pairs (4,5),(6,7)
            unsigned long long bp[4] = {q0.x, q0.y, q1.x, q1.y};
            float am[8] = {a0.x, a0.y, a0.z, a0.w, a1.x, a1.y, a1.z, a1.w};
#pragma unroll
            for (int x = 0; x < 8; x++) {
                unsigned long long ap = pack2(am[x], am[x]);
#pragma unroll
                for (int y = 0; y < 4; y++) fma2(accp[x][y], ap, bp[y]);
            }
        }
        __syncthreads();
    }

    // Epilogue: D[b][j][i] = nb[j] + na[i] - 2*dot
    float nbv[8], nav[8];
#pragma unroll
    for (int x = 0; x < 8; x++) nbv[x] = g_nb[b * MSEQ + rowTile + tm + x];
#pragma unroll
    for (int y = 0; y < 8; y++) nav[y] = g_na[b * NSEQ + colTile + tn + y];

    float* Dp = g_D + ((size_t)b * MSEQ + rowTile + tm) * NSEQ + colTile + tn;
#pragma unroll
    for (int x = 0; x < 8; x++) {
        float2 c0 = unpack2(accp[x][0]);
        float2 c1 = unpack2(accp[x][1]);
        float2 c2 = unpack2(accp[x][2]);
        float2 c3 = unpack2(accp[x][3]);
        float4 o0, o1;
        o0.x = nbv[x] + nav[0] - 2.0f * c0.x;
        o0.y = nbv[x] + nav[1] - 2.0f * c0.y;
        o0.z = nbv[x] + nav[2] - 2.0f * c1.x;
        o0.w = nbv[x] + nav[3] - 2.0f * c1.y;
        o1.x = nbv[x] + nav[4] - 2.0f * c2.x;
        o1.y = nbv[x] + nav[5] - 2.0f * c2.y;
        o1.z = nbv[x] + nav[6] - 2.0f * c3.x;
        o1.w = nbv[x] + nav[7] - 2.0f * c3.y;
        *(float4*)(Dp + (size_t)x * NSEQ)     = o0;
        *(float4*)(Dp + (size_t)x * NSEQ + 4) = o1;
    }
}

// ---------------------------------------------------------------------------
// Kernel 3: soft-DTW wavefront. One CTA per batch, thread t owns column j=t+1.
// D staged through double-buffered smem chunks (CH=12 steps). Each warp stages
// its OWN 32 columns (no cross-warp smem dependency). Warp-activity windows
// skip fully-idle warps; skipped slots provably retain INF.
// ---------------------------------------------------------------------------
#define CH 12
#define CHP 13   // padded row stride (conflict-free: gcd(13,32)=1)

__device__ __forceinline__ void produce_chunk(float* __restrict__ dst,
                                              const float* __restrict__ Db,
                                              int knext, int w, int lane) {
    // warp w stages rows [32w, 32w+32): elements i0 = knext - row - 2 + e, e<CH
    if (lane < 2 * CH) {
        int g = lane / CH;           // 0 or 1 (two rows per iteration)
        int e = lane - g * CH;
#pragma unroll
        for (int rr = 0; rr < 32; rr += 2) {
            int row = (w << 5) + rr + g;
            int i0 = knext - row - 2 + e;
            float v = 0.0f;
            if (i0 >= 0 && i0 < NSEQ) v = Db[row * NSEQ + i0];
            dst[row * CHP + e] = v;
        }
    }
}

__global__ __launch_bounds__(MSEQ) void dtw_kernel(float* __restrict__ out) {
    __shared__ float buf[3][MSEQ + 4];
    __shared__ float Dt[2][MSEQ * CHP];

    const int b = blockIdx.x;
    const int t = threadIdx.x;             // 0..383, column j = t+1
    const int w = t >> 5, lane = t & 31;
    const float* __restrict__ Db = g_D + (size_t)b * MSEQ * NSEQ;

    // warp-activity window: any lane valid  <=>  k in [32w+2, 32w+416]
    const int wk_lo = (w << 5) + 2;
    const int wk_hi = (w << 5) + 32 + NSEQ;

    buf[0][t] = INF_V;
    buf[1][t] = INF_V;
    buf[2][t] = INF_V;
    if (t == 0) {
        buf[0][MSEQ] = INF_V; buf[1][MSEQ] = INF_V; buf[2][MSEQ] = INF_V;
        buf[0][0] = 0.0f;                          // R[0][0]
    }

    // stage first chunk (k in [2, 2+CH)) if this warp will consume it
    if (2 + CH - 1 >= wk_lo) produce_chunk(Dt[0], Db, 2, w, lane);
    __syncthreads();

    int p2 = 0, p1 = 1, pc = 2, cb = 0;

    for (int k0 = 2; k0 <= NSEQ + MSEQ; k0 += CH) {
        // stage next chunk into the other buffer (own warp's rows only)
        int kn = k0 + CH;
        if (kn <= NSEQ + MSEQ && kn + CH - 1 >= wk_lo && kn <= wk_hi)
            produce_chunk(Dt[cb ^ 1], Db, kn, w, lane);

        const float* __restrict__ Dc = &Dt[cb][t * CHP];

#pragma unroll
        for (int c = 0; c < CH; c++) {
            const int k = k0 + c;
            if (k <= NSEQ + MSEQ) {                     // uniform guard
                if (k >= wk_lo && k <= wk_hi) {         // warp-uniform
                    const int i = k - t - 1;
                    if (i >= 1 && i <= NSEQ) {
                        float rd = buf[p2][t];          // diag R[i-1][j-1]
                        float ru = buf[p1][t + 1];      // up   R[i-1][j]
                        float rl = buf[p1][t];          // left R[i][j-1]
                        float d  = Dc[c];
                        float mn = fminf(rd, fminf(ru, rl));
                        float mx = fmaxf(rd, fmaxf(ru, rl));
                        float md = (rd + ru + rl) - mn - mx;
                        float s  = 1.0f + __expf(mn - md) + __expf(mn - mx);
                        float val = d + mn - __logf(s);
                        buf[pc][t + 1] = val;
                        if (k == NSEQ + MSEQ && t == MSEQ - 1) out[b] = val;
                    }
                    if (t == 0) buf[pc][0] = INF_V;     // border R[k][0]
                }
                __syncthreads();
                int tmp = p2; p2 = p1; p1 = pc; pc = tmp;
            }
        }
        cb ^= 1;
    }
}

// ---------------------------------------------------------------------------
// Launch
// ---------------------------------------------------------------------------
extern "C" void kernel_launch(void* const* d_in, const int* in_sizes, int n_in,
                              void* d_out, int out_size) {
    const float* a = (const float*)d_in[0];
    const float* b = (const float*)d_in[1];
    float* out = (float*)d_out;

    norm_kernel<<<(8 * BATCH * NSEQ) / 256, 256>>>(a, b);

    dim3 gdist(NSEQ / BN, MSEQ / BM, BATCH);   // (3,3,128)
    dist_kernel<<<gdist, 256>>>(b, a);

    dtw_kernel<<<BATCH, MSEQ>>>(out);
}

// round 9
// speedup vs baseline: 2.1302x; 1.2529x over previous
#include <cuda_runtime.h>
#include <cuda_bf16.h>
#include <cstdint>

// Problem constants
#define BATCH 128
#define NSEQ  384
#define MSEQ  384
#define DDIM  128
#define INF_V 1000000.0f

// g_D TRANSPOSED: g_D[b][j][i] = ||a_i - b_j||^2, contiguous in i.
__device__ float g_D[(size_t)BATCH * MSEQ * NSEQ];

// ---------------------------------------------------------------------------
// PTX helpers — generic compute_80+ PTX only (harness compiles compute_103
// generic stage; tcgen05/arch-specific ops are NOT available).
// ---------------------------------------------------------------------------
__device__ __forceinline__ uint32_t smem_u32(const void* p) {
    uint32_t a;
    asm("{ .reg .u64 t; cvta.to.shared.u64 t, %1; cvt.u32.u64 %0, t; }" : "=r"(a) : "l"(p));
    return a;
}
__device__ __forceinline__ uint32_t f2bf2(float lo, float hi) {   // pack bf16x2 {hi,lo}
    uint32_t r;
    asm("cvt.rn.bf16x2.f32 %0, %1, %2;" : "=r"(r) : "f"(hi), "f"(lo));
    return r;
}
__device__ __forceinline__ void ldsm4(uint32_t& r0, uint32_t& r1, uint32_t& r2,
                                      uint32_t& r3, uint32_t addr) {
    asm volatile("ldmatrix.sync.aligned.m8n8.x4.shared.b16 {%0,%1,%2,%3}, [%4];"
                 : "=r"(r0), "=r"(r1), "=r"(r2), "=r"(r3) : "r"(addr));
}
__device__ __forceinline__ void mma16816(float* c, const uint32_t* a, const uint32_t* b) {
    asm volatile("mma.sync.aligned.m16n8k16.row.col.f32.bf16.bf16.f32 "
                 "{%0,%1,%2,%3}, {%4,%5,%6,%7}, {%8,%9}, {%0,%1,%2,%3};"
                 : "+f"(c[0]), "+f"(c[1]), "+f"(c[2]), "+f"(c[3])
                 : "r"(a[0]), "r"(a[1]), "r"(a[2]), "r"(a[3]), "r"(b[0]), "r"(b[1]));
}

// ---------------------------------------------------------------------------
// Kernel 1: fused norms + pairwise distances via bf16 HMMA (mma.sync).
// Per CTA: 128(j) x 128(i) tile of one batch.
//   A-operand rows = bf16(-2 * b_j[k])  (M dim = j)
//   B-operand rows = bf16(a_i[k])       (N dim = i, col-major K x N)
//   acc[j][i] = -2 * dot(b_j, a_i);  D[j][i] = nb[j] + na[i] + acc
// K=128 in two 64-halves; smem rows padded to 72 bf16 (144B) -> ldmatrix
// bank-group = row mod 8: conflict-free.
// ---------------------------------------------------------------------------
#define TILE 128
#define KH   64
#define SMSTR 72

struct __align__(16) DistSmem {
    __nv_bfloat16 bmat[TILE * SMSTR];   // A-operand (j rows), 18 KB
    __nv_bfloat16 amat[TILE * SMSTR];   // B-operand (i rows), 18 KB
    float nb[TILE];
    float na[TILE];
};

__global__ __launch_bounds__(256) void dist_kernel(const float* __restrict__ A,
                                                   const float* __restrict__ Bm) {
    __shared__ DistSmem sm;
    const int tid  = threadIdx.x;
    const int wid  = tid >> 5;
    const int lane = tid & 31;
    const int bz    = blockIdx.z;
    const int iTile = blockIdx.x * TILE;
    const int jTile = blockIdx.y * TILE;

    const uint32_t s_b = smem_u32(sm.bmat);
    const uint32_t s_a = smem_u32(sm.amat);

    // staging role: row r (0..127), half-of-row h (32 cols each)
    const int r = tid >> 1;
    const int h = tid & 1;
    const float* arow = A  + ((size_t)bz * NSEQ + iTile + r) * DDIM + h * 32;
    const float* brow = Bm + ((size_t)bz * MSEQ + jTile + r) * DDIM + h * 32;

    // warp tile: 32(j) x 64(i)
    const int j0 = (wid >> 1) * 32;
    const int i0 = (wid & 1) * 64;

    float sa = 0.0f, sb = 0.0f;
    float acc[2][8][4];
#pragma unroll
    for (int fi = 0; fi < 2; fi++)
#pragma unroll
        for (int fn = 0; fn < 8; fn++)
#pragma unroll
            for (int e = 0; e < 4; e++) acc[fi][fn][e] = 0.0f;

    // fixed parts of ldmatrix addresses (in elements)
    const int aAddrRow = j0 + (lane & 15);               // + fi*16
    const int aAddrCol = (lane >> 4) << 3;               // + koff
    const int bAddrRow = i0 + ((lane >> 4) << 3) + (lane & 7);   // + g*16
    const int bAddrCol = ((lane >> 3) & 1) << 3;         // + koff

#pragma unroll
    for (int half = 0; half < 2; half++) {
        const int k0 = half * KH;
        // stage this K-half as bf16; accumulate norms from fp32
#pragma unroll
        for (int i = 0; i < 8; i++) {
            const int col = h * 32 + i * 4;
            float4 va = *(const float4*)(arow + k0 + i * 4);
            sa += va.x * va.x + va.y * va.y + va.z * va.z + va.w * va.w;
            *(uint2*)&sm.amat[r * SMSTR + col] =
                make_uint2(f2bf2(va.x, va.y), f2bf2(va.z, va.w));
            float4 vb = *(const float4*)(brow + k0 + i * 4);
            sb += vb.x * vb.x + vb.y * vb.y + vb.z * vb.z + vb.w * vb.w;
            *(uint2*)&sm.bmat[r * SMSTR + col] =
                make_uint2(f2bf2(-2.0f * vb.x, -2.0f * vb.y),
                           f2bf2(-2.0f * vb.z, -2.0f * vb.w));
        }
        __syncthreads();

#pragma unroll
        for (int kk = 0; kk < 4; kk++) {
            const int koff = kk * 16;
            uint32_t af[2][4];
#pragma unroll
            for (int fi = 0; fi < 2; fi++)
                ldsm4(af[fi][0], af[fi][1], af[fi][2], af[fi][3],
                      s_b + (uint32_t)(((aAddrRow + fi * 16) * SMSTR + koff + aAddrCol) * 2));
            uint32_t bf[8][2];
#pragma unroll
            for (int g = 0; g < 4; g++) {
                uint32_t q0, q1, q2, q3;
                ldsm4(q0, q1, q2, q3,
                      s_a + (uint32_t)(((bAddrRow + g * 16) * SMSTR + koff + bAddrCol) * 2));
                bf[2 * g][0] = q0; bf[2 * g][1] = q1;
                bf[2 * g + 1][0] = q2; bf[2 * g + 1][1] = q3;
            }
#pragma unroll
            for (int fi = 0; fi < 2; fi++)
#pragma unroll
                for (int fn = 0; fn < 8; fn++)
                    mma16816(acc[fi][fn], af[fi], bf[fn]);
        }
        __syncthreads();   // ldmatrix done before restage / norms
    }

    // norms: pair-reduce the two 64-col halves (lanes tid^1 in same warp)
    sa += __shfl_xor_sync(0xffffffffu, sa, 1);
    sb += __shfl_xor_sync(0xffffffffu, sb, 1);
    if (h == 0) { sm.na[r] = sa; sm.nb[r] = sb; }
    __syncthreads();

    // Epilogue: D[j][i] = nb[j] + na[i] + acc ; pairwise float2 stores.
    // acc layout: c0 (jq, ip), c1 (jq, ip+1), c2 (jq+8, ip), c3 (jq+8, ip+1)
    const int jq = lane >> 2;          // 0..7
    const int ip = (lane & 3) * 2;
    float* Drow = g_D + ((size_t)bz * MSEQ + jTile) * NSEQ + iTile;
#pragma unroll
    for (int fi = 0; fi < 2; fi++) {
        const int jl = j0 + fi * 16 + jq;
        const float nb0 = sm.nb[jl];
        const float nb1 = sm.nb[jl + 8];
#pragma unroll
        for (int fn = 0; fn < 8; fn++) {
            const int il = i0 + fn * 8 + ip;
            const float na0 = sm.na[il];
            const float na1 = sm.na[il + 1];
            float2 v0 = make_float2(nb0 + na0 + acc[fi][fn][0],
                                    nb0 + na1 + acc[fi][fn][1]);
            float2 v1 = make_float2(nb1 + na0 + acc[fi][fn][2],
                                    nb1 + na1 + acc[fi][fn][3]);
            *(float2*)&Drow[(size_t)jl * NSEQ + il]       = v0;
            *(float2*)&Drow[(size_t)(jl + 8) * NSEQ + il] = v1;
        }
    }
}

// ---------------------------------------------------------------------------
// Kernel 2: soft-DTW wavefront (unchanged from R4). One CTA per batch.
// ---------------------------------------------------------------------------
#define CH 12
#define CHP 13

__device__ __forceinline__ void produce_chunk(float* __restrict__ dst,
                                              const float* __restrict__ Db,
                                              int knext, int w, int lane) {
    if (lane < 2 * CH) {
        int g = lane / CH;
        int e = lane - g * CH;
#pragma unroll
        for (int rr = 0; rr < 32; rr += 2) {
            int row = (w << 5) + rr + g;
            int i0 = knext - row - 2 + e;
            float v = 0.0f;
            if (i0 >= 0 && i0 < NSEQ) v = Db[row * NSEQ + i0];
            dst[row * CHP + e] = v;
        }
    }
}

__global__ __launch_bounds__(MSEQ) void dtw_kernel(float* __restrict__ out) {
    __shared__ float buf[3][MSEQ + 4];
    __shared__ float Dt[2][MSEQ * CHP];

    const int b = blockIdx.x;
    const int t = threadIdx.x;
    const int w = t >> 5, lane = t & 31;
    const float* __restrict__ Db = g_D + (size_t)b * MSEQ * NSEQ;

    const int wk_lo = (w << 5) + 2;
    const int wk_hi = (w << 5) + 32 + NSEQ;

    buf[0][t] = INF_V;
    buf[1][t] = INF_V;
    buf[2][t] = INF_V;
    if (t == 0) {
        buf[0][MSEQ] = INF_V; buf[1][MSEQ] = INF_V; buf[2][MSEQ] = INF_V;
        buf[0][0] = 0.0f;
    }

    if (2 + CH - 1 >= wk_lo) produce_chunk(Dt[0], Db, 2, w, lane);
    __syncthreads();

    int p2 = 0, p1 = 1, pc = 2, cb = 0;

    for (int k0 = 2; k0 <= NSEQ + MSEQ; k0 += CH) {
        int kn = k0 + CH;
        if (kn <= NSEQ + MSEQ && kn + CH - 1 >= wk_lo && kn <= wk_hi)
            produce_chunk(Dt[cb ^ 1], Db, kn, w, lane);

        const float* __restrict__ Dc = &Dt[cb][t * CHP];

#pragma unroll
        for (int c = 0; c < CH; c++) {
            const int k = k0 + c;
            if (k <= NSEQ + MSEQ) {
                if (k >= wk_lo && k <= wk_hi) {
                    const int i = k - t - 1;
                    if (i >= 1 && i <= NSEQ) {
                        float rd = buf[p2][t];
                        float ru = buf[p1][t + 1];
                        float rl = buf[p1][t];
                        float d  = Dc[c];
                        float mn = fminf(rd, fminf(ru, rl));
                        float mx = fmaxf(rd, fmaxf(ru, rl));
                        float md = (rd + ru + rl) - mn - mx;
                        float s  = 1.0f + __expf(mn - md) + __expf(mn - mx);
                        float val = d + mn - __logf(s);
                        buf[pc][t + 1] = val;
                        if (k == NSEQ + MSEQ && t == MSEQ - 1) out[b] = val;
                    }
                    if (t == 0) buf[pc][0] = INF_V;
                }
                __syncthreads();
                int tmp = p2; p2 = p1; p1 = pc; pc = tmp;
            }
        }
        cb ^= 1;
    }
}

// ---------------------------------------------------------------------------
// Launch
// ---------------------------------------------------------------------------
extern "C" void kernel_launch(void* const* d_in, const int* in_sizes, int n_in,
                              void* d_out, int out_size) {
    const float* a = (const float*)d_in[0];
    const float* b = (const float*)d_in[1];
    float* out = (float*)d_out;

    dim3 gdist(NSEQ / TILE, MSEQ / TILE, BATCH);   // (3,3,128)
    dist_kernel<<<gdist, 256>>>(a, b);

    dtw_kernel<<<BATCH, MSEQ>>>(out);
}

// round 11
// speedup vs baseline: 3.6353x; 1.7065x over previous
#include <cuda_runtime.h>
#include <cuda_bf16.h>
#include <cstdint>

// Problem constants
#define BATCH 128
#define NSEQ  384
#define MSEQ  384
#define DDIM  128
#define INF_V 1000000.0f

// g_D TRANSPOSED: g_D[b][j][i] = ||a_i - b_j||^2, contiguous in i.
__device__ float g_D[(size_t)BATCH * MSEQ * NSEQ];

// ---------------------------------------------------------------------------
// PTX helpers — generic compute_80+ PTX only (compute_103 generic stage;
// tcgen05 / arch-specific ops are NOT available in this devloop).
// ---------------------------------------------------------------------------
__device__ __forceinline__ uint32_t smem_u32(const void* p) {
    uint32_t a;
    asm("{ .reg .u64 t; cvta.to.shared.u64 t, %1; cvt.u32.u64 %0, t; }" : "=r"(a) : "l"(p));
    return a;
}
__device__ __forceinline__ uint32_t f2bf2(float lo, float hi) {   // pack bf16x2 {hi,lo}
    uint32_t r;
    asm("cvt.rn.bf16x2.f32 %0, %1, %2;" : "=r"(r) : "f"(hi), "f"(lo));
    return r;
}
__device__ __forceinline__ void ldsm4(uint32_t& r0, uint32_t& r1, uint32_t& r2,
                                      uint32_t& r3, uint32_t addr) {
    asm volatile("ldmatrix.sync.aligned.m8n8.x4.shared.b16 {%0,%1,%2,%3}, [%4];"
                 : "=r"(r0), "=r"(r1), "=r"(r2), "=r"(r3) : "r"(addr));
}
__device__ __forceinline__ void mma16816(float* c, const uint32_t* a, const uint32_t* b) {
    asm volatile("mma.sync.aligned.m16n8k16.row.col.f32.bf16.bf16.f32 "
                 "{%0,%1,%2,%3}, {%4,%5,%6,%7}, {%8,%9}, {%0,%1,%2,%3};"
                 : "+f"(c[0]), "+f"(c[1]), "+f"(c[2]), "+f"(c[3])
                 : "r"(a[0]), "r"(a[1]), "r"(a[2]), "r"(a[3]), "r"(b[0]), "r"(b[1]));
}
__device__ __forceinline__ void cp_async4(uint32_t dst, const void* src, uint32_t srcsz) {
    asm volatile("cp.async.ca.shared.global [%0], [%1], 4, %2;"
                 :: "r"(dst), "l"(src), "r"(srcsz) : "memory");
}
#define CP_COMMIT() asm volatile("cp.async.commit_group;" ::: "memory")
#define CP_WAIT0()  asm volatile("cp.async.wait_group 0;" ::: "memory")

// ---------------------------------------------------------------------------
// Kernel 1: fused norms + pairwise distances via bf16 HMMA (unchanged R9).
// ---------------------------------------------------------------------------
#define TILE 128
#define KH   64
#define SMSTR 72

struct __align__(16) DistSmem {
    __nv_bfloat16 bmat[TILE * SMSTR];
    __nv_bfloat16 amat[TILE * SMSTR];
    float nb[TILE];
    float na[TILE];
};

__global__ __launch_bounds__(256) void dist_kernel(const float* __restrict__ A,
                                                   const float* __restrict__ Bm) {
    __shared__ DistSmem sm;
    const int tid  = threadIdx.x;
    const int wid  = tid >> 5;
    const int lane = tid & 31;
    const int bz    = blockIdx.z;
    const int iTile = blockIdx.x * TILE;
    const int jTile = blockIdx.y * TILE;

    const uint32_t s_b = smem_u32(sm.bmat);
    const uint32_t s_a = smem_u32(sm.amat);

    const int r = tid >> 1;
    const int h = tid & 1;
    const float* arow = A  + ((size_t)bz * NSEQ + iTile + r) * DDIM + h * 32;
    const float* brow = Bm + ((size_t)bz * MSEQ + jTile + r) * DDIM + h * 32;

    const int j0 = (wid >> 1) * 32;
    const int i0 = (wid & 1) * 64;

    float sa = 0.0f, sb = 0.0f;
    float acc[2][8][4];
#pragma unroll
    for (int fi = 0; fi < 2; fi++)
#pragma unroll
        for (int fn = 0; fn < 8; fn++)
#pragma unroll
            for (int e = 0; e < 4; e++) acc[fi][fn][e] = 0.0f;

    const int aAddrRow = j0 + (lane & 15);
    const int aAddrCol = (lane >> 4) << 3;
    const int bAddrRow = i0 + ((lane >> 4) << 3) + (lane & 7);
    const int bAddrCol = ((lane >> 3) & 1) << 3;

#pragma unroll
    for (int half = 0; half < 2; half++) {
        const int k0 = half * KH;
#pragma unroll
        for (int i = 0; i < 8; i++) {
            const int col = h * 32 + i * 4;
            float4 va = *(const float4*)(arow + k0 + i * 4);
            sa += va.x * va.x + va.y * va.y + va.z * va.z + va.w * va.w;
            *(uint2*)&sm.amat[r * SMSTR + col] =
                make_uint2(f2bf2(va.x, va.y), f2bf2(va.z, va.w));
            float4 vb = *(const float4*)(brow + k0 + i * 4);
            sb += vb.x * vb.x + vb.y * vb.y + vb.z * vb.z + vb.w * vb.w;
            *(uint2*)&sm.bmat[r * SMSTR + col] =
                make_uint2(f2bf2(-2.0f * vb.x, -2.0f * vb.y),
                           f2bf2(-2.0f * vb.z, -2.0f * vb.w));
        }
        __syncthreads();

#pragma unroll
        for (int kk = 0; kk < 4; kk++) {
            const int koff = kk * 16;
            uint32_t af[2][4];
#pragma unroll
            for (int fi = 0; fi < 2; fi++)
                ldsm4(af[fi][0], af[fi][1], af[fi][2], af[fi][3],
                      s_b + (uint32_t)(((aAddrRow + fi * 16) * SMSTR + koff + aAddrCol) * 2));
            uint32_t bf[8][2];
#pragma unroll
            for (int g = 0; g < 4; g++) {
                uint32_t q0, q1, q2, q3;
                ldsm4(q0, q1, q2, q3,
                      s_a + (uint32_t)(((bAddrRow + g * 16) * SMSTR + koff + bAddrCol) * 2));
                bf[2 * g][0] = q0; bf[2 * g][1] = q1;
                bf[2 * g + 1][0] = q2; bf[2 * g + 1][1] = q3;
            }
#pragma unroll
            for (int fi = 0; fi < 2; fi++)
#pragma unroll
                for (int fn = 0; fn < 8; fn++)
                    mma16816(acc[fi][fn], af[fi], bf[fn]);
        }
        __syncthreads();
    }

    sa += __shfl_xor_sync(0xffffffffu, sa, 1);
    sb += __shfl_xor_sync(0xffffffffu, sb, 1);
    if (h == 0) { sm.na[r] = sa; sm.nb[r] = sb; }
    __syncthreads();

    const int jq = lane >> 2;
    const int ip = (lane & 3) * 2;
    float* Drow = g_D + ((size_t)bz * MSEQ + jTile) * NSEQ + iTile;
#pragma unroll
    for (int fi = 0; fi < 2; fi++) {
        const int jl = j0 + fi * 16 + jq;
        const float nb0 = sm.nb[jl];
        const float nb1 = sm.nb[jl + 8];
#pragma unroll
        for (int fn = 0; fn < 8; fn++) {
            const int il = i0 + fn * 8 + ip;
            const float na0 = sm.na[il];
            const float na1 = sm.na[il + 1];
            float2 v0 = make_float2(nb0 + na0 + acc[fi][fn][0],
                                    nb0 + na1 + acc[fi][fn][1]);
            float2 v1 = make_float2(nb1 + na0 + acc[fi][fn][2],
                                    nb1 + na1 + acc[fi][fn][3]);
            *(float2*)&Drow[(size_t)jl * NSEQ + il]       = v0;
            *(float2*)&Drow[(size_t)(jl + 8) * NSEQ + il] = v1;
        }
    }
}

// ---------------------------------------------------------------------------
// Kernel 2: soft-DTW wavefront, TWO diagonals per barrier + cp.async staging.
// Thread t owns column j=t+1. buf[g&3][c] = R[g-c, c] (4-slot rotation;
// gens k-2..k+1 live per pair).
// Pair (k even, k+1): step k from smem; step k+1 entirely from registers:
//   up = val1, diag = rl (step-k left), left = shfl_up(val1)
//   (lane 0 computes the warp-boundary column redundantly from synced smem).
// Pseudo-INF (1e6) keeps all arithmetic finite; invalid cells select to INF.
// ---------------------------------------------------------------------------
#define CH 12
#define CHP 13

__device__ __forceinline__ float softmin_cell(float rd, float ru, float rl, float d) {
    float mn = fminf(rd, fminf(ru, rl));
    float mx = fmaxf(rd, fmaxf(ru, rl));
    float md = (rd + ru + rl) - mn - mx;
    float s  = 1.0f + __expf(mn - md) + __expf(mn - mx);
    return d + (mn - __logf(s));
}

__global__ __launch_bounds__(384) void dtw_kernel(float* __restrict__ out) {
    __shared__ float buf[4][MSEQ + 4];
    __shared__ float Dt[2][MSEQ * CHP];

    const int b = blockIdx.x;
    const int t = threadIdx.x;               // column j = t+1
    const int w = t >> 5, lane = t & 31;
    const float* __restrict__ Db = g_D + (size_t)b * MSEQ * NSEQ;

    const int wk_lo = (w << 5) + 2;          // first diagonal with any valid lane
    const int wk_hi = (w << 5) + 32 + NSEQ;  // last

    // staging roles: lanes 0..23 cover 2 rows x 12 elements per pass
    const int sg = lane / CH;                // 0/1
    const int se = lane - sg * CH;           // 0..11
    const bool stager = (lane < 2 * CH);

    // stage chunk 0 (diagonals 2..13) — only warps whose window overlaps
    if (stager && 2 + CH - 1 >= wk_lo) {
        for (int rr = 0; rr < 32; rr += 2) {
            int row = (w << 5) + rr + sg;
            int i0 = 0 - row + se;           // kn=2: i0 = 2 - row - 2 + se
            uint32_t ok = (i0 >= 0 && i0 < NSEQ) ? 4u : 0u;
            const float* src = Db + (size_t)row * NSEQ + (i0 < 0 ? 0 : i0);
            cp_async4(smem_u32(&Dt[0][row * CHP + se]), src, ok);
        }
    }
    CP_COMMIT();

    buf[0][t] = INF_V; buf[1][t] = INF_V; buf[2][t] = INF_V; buf[3][t] = INF_V;
    if (t == 0) {
        buf[0][MSEQ] = INF_V; buf[1][MSEQ] = INF_V;
        buf[2][MSEQ] = INF_V; buf[3][MSEQ] = INF_V;
        buf[0][0] = 0.0f;                    // R[0][0]
    }
    CP_WAIT0();
    __syncthreads();

    int cb = 0;
    for (int m = 0; m < 64; m++) {           // 64 chunks x 12 diagonals (k=2..769)
        const int k0 = 2 + m * CH;
        const int kn = k0 + CH;
        if (m < 63 && stager && kn + CH - 1 >= wk_lo && kn <= wk_hi) {
            float* dst = Dt[cb ^ 1];
            for (int rr = 0; rr < 32; rr += 2) {
                int row = (w << 5) + rr + sg;
                int i0 = kn - row - 2 + se;
                uint32_t ok = (i0 >= 0 && i0 < NSEQ) ? 4u : 0u;
                const float* src = Db + (size_t)row * NSEQ + (i0 < 0 ? 0 : i0);
                cp_async4(smem_u32(&dst[row * CHP + se]), src, ok);
            }
        }
        CP_COMMIT();

        const float* __restrict__ Dc = Dt[cb];
#pragma unroll
        for (int p = 0; p < 6; p++) {
            const int k = k0 + 2 * p;                    // even
            const int s0 = k & 3, s1 = (k + 1) & 3;
            const int sp1 = (k - 1) & 3, sp2 = (k - 2) & 3;
            if (k + 1 >= wk_lo && k <= wk_hi) {          // warp-uniform window
                const int i1 = k - t - 1;
                // ---- step k (smem) ----
                float rd = buf[sp2][t];                  // diag
                float ru = buf[sp1][t + 1];              // up
                float rl = buf[sp1][t];                  // left
                float d1 = Dc[t * CHP + 2 * p];
                float v1 = softmin_cell(rd, ru, rl, d1);
                float val1 = (i1 >= 1 && i1 <= NSEQ) ? v1 : INF_V;
                // lane 0: redundant boundary column jr = 32w (= warp w-1 lane 31's cell)
                float valr = INF_V;
                if (lane == 0 && w > 0) {
                    const int ir = i1 + 1;               // i at column jr = t
                    if (ir >= 1 && ir <= NSEQ) {
                        float rdr = buf[sp2][t - 1];
                        float rlr = buf[sp1][t - 1];
                        float drr = Dc[(t - 1) * CHP + 2 * p];
                        valr = softmin_cell(rdr, rl, rlr, drr);
                    }
                }
                // ---- step k+1 (registers + shfl) ----
                float left2 = __shfl_up_sync(0xffffffffu, val1, 1);
                if (lane == 0) left2 = valr;
                float d2 = Dc[t * CHP + 2 * p + 1];
                float v2 = softmin_cell(rl, val1, left2, d2);   // diag=rl, up=val1
                const int i2 = i1 + 1;
                float val2 = (i2 >= 1 && i2 <= NSEQ) ? v2 : INF_V;

                buf[s0][t + 1] = val1;
                buf[s1][t + 1] = val2;
                if (t == 0) { buf[s0][0] = INF_V; buf[s1][0] = INF_V; }
                if (k == NSEQ + MSEQ && t == MSEQ - 1) out[b] = val1;  // R[N][M]
            }
            __syncthreads();
        }
        CP_WAIT0();          // next chunk's copies done (all warps) ...
        __syncthreads();     // ... and visible cross-warp
        cb ^= 1;
    }
}

// ---------------------------------------------------------------------------
// Launch
// ---------------------------------------------------------------------------
extern "C" void kernel_launch(void* const* d_in, const int* in_sizes, int n_in,
                              void* d_out, int out_size) {
    const float* a = (const float*)d_in[0];
    const float* b = (const float*)d_in[1];
    float* out = (float*)d_out;

    dim3 gdist(NSEQ / TILE, MSEQ / TILE, BATCH);   // (3,3,128)
    dist_kernel<<<gdist, 256>>>(a, b);

    dtw_kernel<<<BATCH, 384>>>(out);
}